// round 2
// baseline (speedup 1.0000x reference)
#include <cuda_runtime.h>
#include <cstdint>

// KeyValueBottleneck: b=32, C=64, n=64, dk=dv=16, J=1024
// out = concat(qv[2097152], new_keys[1048576], new_cluster_size[65536], new_keys_avg[1048576])

#define DECAY 0.95f
#define OMD   0.05f      // 1 - DECAY
#define EPSV  1e-5f

constexpr int Cc = 64, Bb = 32, Nn = 64, DK = 16, J = 1024;
constexpr int OFF_QV   = 0;
constexpr int OFF_KEYS = 2097152;                 // b*C*n*dv
constexpr int OFF_CS   = OFF_KEYS + Cc * J * DK;  // 3145728
constexpr int OFF_KA   = OFF_CS + Cc * J;         // 3211264
constexpr int TJ = 128;                           // keys per shared tile

// ---------------- packed f32x2 helpers (Blackwell-only, PTX) ----------------
__device__ __forceinline__ uint64_t pack2(float a, float b) {
    uint64_t r;
    asm("mov.b64 %0, {%1, %2};" : "=l"(r) : "f"(a), "f"(b));
    return r;
}
__device__ __forceinline__ void unpack2(uint64_t v, float& a, float& b) {
    asm("mov.b64 {%0, %1}, %2;" : "=f"(a), "=f"(b) : "l"(v));
}
__device__ __forceinline__ void ffma2(uint64_t& d, uint64_t a, uint64_t b) {
    asm("fma.rn.f32x2 %0, %1, %2, %0;" : "+l"(d) : "l"(a), "l"(b));
}

// ---------------- kernel 0: seed EMA output regions --------------------------
// out_cs = cluster_size * DECAY ; out_ka = keys_avg * DECAY  (float4 vectorized)
__global__ __launch_bounds__(256) void k_init(const float4* __restrict__ keys_avg,
                                              const float4* __restrict__ cs,
                                              float4* __restrict__ out4) {
    int i = blockIdx.x * 256 + threadIdx.x;  // grid covers 262144 float4
    if (i < (Cc * J * DK) / 4) {
        float4 v = keys_avg[i];
        v.x *= DECAY; v.y *= DECAY; v.z *= DECAY; v.w *= DECAY;
        out4[OFF_KA / 4 + i] = v;
    }
    if (i < (Cc * J) / 4) {
        float4 v = cs[i];
        v.x *= DECAY; v.y *= DECAY; v.z *= DECAY; v.w *= DECAY;
        out4[OFF_CS / 4 + i] = v;
    }
}

// ---------------- kernel 1: assignment + qv gather + EMA atomics -------------
// grid: 256 blocks (4 per channel), 256 threads, 2 points/thread (512 pts/blk)
__global__ __launch_bounds__(256) void k_assign(const float* __restrict__ x,
                                                const float* __restrict__ keys,
                                                const float* __restrict__ values,
                                                float* __restrict__ out) {
    __shared__ __align__(16) float skey[TJ * 16];  // 8 KB key tile
    __shared__ float skk[TJ];                      // ||k||^2 per key

    const int t = threadIdx.x;
    const int c = blockIdx.x >> 2;
    const int ibase = (blockIdx.x & 3) * 512;

    // Load this thread's 2 points; keep packed (f32x2 per dim-pair) + ||x||^2.
    uint64_t xp[2][8];
    float    xx[2];
    int      fi[2];
#pragma unroll
    for (int p = 0; p < 2; p++) {
        int i  = ibase + t + p * 256;         // point index in [0, 2048)
        int bb = i >> 6, ni = i & 63;
        int fidx = ((bb * Cc + c) * Nn + ni) * DK;  // float index into x (and qv out)
        fi[p] = fidx;
        const float4* xs = reinterpret_cast<const float4*>(x + fidx);
        float s = 0.f;
#pragma unroll
        for (int q = 0; q < 4; q++) {
            float4 v = xs[q];
            s += v.x * v.x + v.y * v.y + v.z * v.z + v.w * v.w;
            xp[p][2 * q]     = pack2(v.x, v.y);
            xp[p][2 * q + 1] = pack2(v.z, v.w);
        }
        xx[p] = s;
    }

    float best0 = 3.402823466e38f, best1 = 3.402823466e38f;
    int   bj0 = 0, bj1 = 0;

    for (int j0 = 0; j0 < J; j0 += TJ) {
        __syncthreads();  // protect previous tile reads
        // cooperative tile load: TJ*16 floats = 512 float4, 2 per thread
        const float4* ks = reinterpret_cast<const float4*>(keys + ((size_t)c * J + j0) * DK);
        reinterpret_cast<float4*>(skey)[t]       = ks[t];
        reinterpret_cast<float4*>(skey)[t + 256] = ks[t + 256];
        __syncthreads();
        if (t < TJ) {
            const float* kv = skey + t * 16;
            float s = 0.f;
#pragma unroll
            for (int d = 0; d < 16; d++) s += kv[d] * kv[d];
            skk[t] = s;
        }
        __syncthreads();

        const ulonglong2* sk2 = reinterpret_cast<const ulonglong2*>(skey);
#pragma unroll 8
        for (int jj = 0; jj < TJ; jj++) {
            // two accumulator chains per point for ILP
            uint64_t a0a = 0ull, a0b = 0ull, a1a = 0ull, a1b = 0ull;
#pragma unroll
            for (int q = 0; q < 2; q++) {
                ulonglong2 kq = sk2[jj * 4 + q];
                ffma2(a0a, xp[0][2 * q],     kq.x);
                ffma2(a0a, xp[0][2 * q + 1], kq.y);
                ffma2(a1a, xp[1][2 * q],     kq.x);
                ffma2(a1a, xp[1][2 * q + 1], kq.y);
            }
#pragma unroll
            for (int q = 2; q < 4; q++) {
                ulonglong2 kq = sk2[jj * 4 + q];
                ffma2(a0b, xp[0][2 * q],     kq.x);
                ffma2(a0b, xp[0][2 * q + 1], kq.y);
                ffma2(a1b, xp[1][2 * q],     kq.x);
                ffma2(a1b, xp[1][2 * q + 1], kq.y);
            }
            float kk = skk[jj];
            float u, v, w, z;
            unpack2(a0a, u, v); unpack2(a0b, w, z);
            float s0 = fmaf(-2.f, (u + v) + (w + z), xx[0] + kk);
            unpack2(a1a, u, v); unpack2(a1b, w, z);
            float s1 = fmaf(-2.f, (u + v) + (w + z), xx[1] + kk);
            int j = j0 + jj;
            if (s0 < best0) { best0 = s0; bj0 = j; }  // strict < => first-index ties
            if (s1 < best1) { best1 = s1; bj1 = j; }
        }
    }

    // Epilogue: gather values -> qv, EMA atomic adds.
    int bj[2] = { bj0, bj1 };
#pragma unroll
    for (int p = 0; p < 2; p++) {
        int j = bj[p];
        const float4* vs = reinterpret_cast<const float4*>(values + ((size_t)c * J + j) * DK);
        float4* qd = reinterpret_cast<float4*>(out + OFF_QV + fi[p]);
#pragma unroll
        for (int q = 0; q < 4; q++) qd[q] = vs[q];

        atomicAdd(out + OFF_CS + c * J + j, OMD);
        float* ka = out + OFF_KA + ((size_t)(c * J + j)) * DK;
#pragma unroll
        for (int q = 0; q < 8; q++) {
            float a, b;
            unpack2(xp[p][q], a, b);
            atomicAdd(ka + 2 * q,     OMD * a);
            atomicAdd(ka + 2 * q + 1, OMD * b);
        }
    }
}

// ---------------- kernel 2: finalize new_keys --------------------------------
// per channel: tot = sum(new_cs); new_keys = new_ka / ((new_cs+eps)/(tot+J*eps)*tot)
__global__ __launch_bounds__(256) void k_final(float* __restrict__ out) {
    __shared__ float sred[256];
    const int c = blockIdx.x, t = threadIdx.x;
    const float* ncs = out + OFF_CS + c * J;

    float part = 0.f;
    for (int j = t; j < J; j += 256) part += ncs[j];
    sred[t] = part;
    __syncthreads();
    for (int s = 128; s > 0; s >>= 1) {
        if (t < s) sred[t] += sred[t + s];
        __syncthreads();
    }
    const float tot = sred[0];
    const float scale = tot / (tot + (float)J * EPSV);

    for (int j = t; j < J; j += 256) {
        float cssm = (ncs[j] + EPSV) * scale;
        float inv = 1.0f / cssm;
        const float4* ka = reinterpret_cast<const float4*>(out + OFF_KA + (size_t)(c * J + j) * DK);
        float4* nk = reinterpret_cast<float4*>(out + OFF_KEYS + (size_t)(c * J + j) * DK);
#pragma unroll
        for (int q = 0; q < 4; q++) {
            float4 v = ka[q];
            v.x *= inv; v.y *= inv; v.z *= inv; v.w *= inv;
            nk[q] = v;
        }
    }
}

extern "C" void kernel_launch(void* const* d_in, const int* in_sizes, int n_in,
                              void* d_out, int out_size) {
    const float* x        = (const float*)d_in[0];
    const float* keys     = (const float*)d_in[1];
    const float* values   = (const float*)d_in[2];
    const float* keys_avg = (const float*)d_in[3];
    const float* cs       = (const float*)d_in[4];
    float* out = (float*)d_out;

    k_init<<<1024, 256>>>((const float4*)keys_avg, (const float4*)cs, (float4*)out);
    k_assign<<<256, 256>>>(x, keys, values, out);
    k_final<<<64, 256>>>(out);
}

// round 3
// speedup vs baseline: 1.0255x; 1.0255x over previous
#include <cuda_runtime.h>
#include <cstdint>

// KeyValueBottleneck: b=32, C=64, n=64, dk=dv=16, J=1024
// out = concat(qv[2097152], new_keys[1048576], new_cluster_size[65536], new_keys_avg[1048576])

#define DECAY 0.95f
#define OMD   0.05f      // 1 - DECAY
#define EPSV  1e-5f

constexpr int Cc = 64, Nn = 64, DK = 16, J = 1024;
constexpr int OFF_QV   = 0;
constexpr int OFF_KEYS = 2097152;                 // b*C*n*dv
constexpr int OFF_CS   = OFF_KEYS + Cc * J * DK;  // 3145728
constexpr int OFF_KA   = OFF_CS + Cc * J;         // 3211264
constexpr int TJ = 128;                           // keys per shared tile

// ---------------- packed f32x2 helpers (Blackwell-only, PTX) ----------------
__device__ __forceinline__ uint64_t pack2(float a, float b) {
    uint64_t r;
    asm("mov.b64 %0, {%1, %2};" : "=l"(r) : "f"(a), "f"(b));
    return r;
}
__device__ __forceinline__ void unpack2(uint64_t v, float& a, float& b) {
    asm("mov.b64 {%0, %1}, %2;" : "=f"(a), "=f"(b) : "l"(v));
}
__device__ __forceinline__ void ffma2(uint64_t& d, uint64_t a, uint64_t b) {
    asm("fma.rn.f32x2 %0, %1, %2, %0;" : "+l"(d) : "l"(a), "l"(b));
}
__device__ __forceinline__ uint64_t add2(uint64_t a, uint64_t b) {
    uint64_t r;
    asm("add.rn.f32x2 %0, %1, %2;" : "=l"(r) : "l"(a), "l"(b));
    return r;
}

// ---------------- kernel 0: seed EMA output regions --------------------------
__global__ __launch_bounds__(256) void k_init(const float4* __restrict__ keys_avg,
                                              const float4* __restrict__ cs,
                                              float4* __restrict__ out4) {
    int i = blockIdx.x * 256 + threadIdx.x;  // grid covers 262144 float4
    if (i < (Cc * J * DK) / 4) {
        float4 v = keys_avg[i];
        v.x *= DECAY; v.y *= DECAY; v.z *= DECAY; v.w *= DECAY;
        out4[OFF_KA / 4 + i] = v;
    }
    if (i < (Cc * J) / 4) {
        float4 v = cs[i];
        v.x *= DECAY; v.y *= DECAY; v.z *= DECAY; v.w *= DECAY;
        out4[OFF_CS / 4 + i] = v;
    }
}

// ---------------- kernel 1: assignment + qv gather + EMA atomics -------------
// grid: 512 blocks (8 per channel), 128 threads, 2 points/thread (256 pts/blk).
// Single wave on 148 SMs (~6-7 blocks/SM resident), 24+ warps/SM.
// Score: argmax_j ( x . k_j  -  0.5*||k_j||^2 )  ==  reference argmax(-dist).
__global__ __launch_bounds__(128) void k_assign(const float* __restrict__ x,
                                                const float* __restrict__ keys,
                                                const float* __restrict__ values,
                                                float* __restrict__ out) {
    __shared__ __align__(16) float skey[TJ * 16];  // 8 KB key tile
    __shared__ float shkk[TJ];                     // -0.5*||k||^2 per key

    const int t = threadIdx.x;
    const int c = blockIdx.x >> 3;
    const int ibase = (blockIdx.x & 7) * 256;

    // Load this thread's 2 points; keep packed (f32x2 per dim-pair).
    uint64_t xp[2][8];
    int      fi[2];
#pragma unroll
    for (int p = 0; p < 2; p++) {
        int i  = ibase + t + p * 128;               // point index in [0, 2048)
        int bb = i >> 6, ni = i & 63;
        int fidx = ((bb * Cc + c) * Nn + ni) * DK;  // float index into x (and qv out)
        fi[p] = fidx;
        const float4* xs = reinterpret_cast<const float4*>(x + fidx);
#pragma unroll
        for (int q = 0; q < 4; q++) {
            float4 v = xs[q];
            xp[p][2 * q]     = pack2(v.x, v.y);
            xp[p][2 * q + 1] = pack2(v.z, v.w);
        }
    }

    float best0 = -3.402823466e38f, best1 = -3.402823466e38f;
    int   bj0 = 0, bj1 = 0;

    for (int j0 = 0; j0 < J; j0 += TJ) {
        __syncthreads();  // protect previous tile reads
        // cooperative tile load: TJ*16 floats = 512 float4, 4 per thread
        const float4* ks = reinterpret_cast<const float4*>(keys + ((size_t)c * J + j0) * DK);
        float4* sk4 = reinterpret_cast<float4*>(skey);
#pragma unroll
        for (int r = 0; r < 4; r++) sk4[t + 128 * r] = ks[t + 128 * r];
        __syncthreads();
        {   // each thread: -0.5*||k_t||^2
            const float* kv = skey + t * 16;
            float s = 0.f;
#pragma unroll
            for (int d = 0; d < 16; d++) s += kv[d] * kv[d];
            shkk[t] = -0.5f * s;
        }
        __syncthreads();

        const ulonglong2* sk2 = reinterpret_cast<const ulonglong2*>(skey);
#pragma unroll 4
        for (int jj = 0; jj < TJ; jj++) {
            // two accumulator chains per point for ILP
            uint64_t a0a = 0ull, a0b = 0ull, a1a = 0ull, a1b = 0ull;
#pragma unroll
            for (int q = 0; q < 2; q++) {
                ulonglong2 kq = sk2[jj * 4 + q];       // broadcast (conflict-free)
                ffma2(a0a, xp[0][2 * q],     kq.x);
                ffma2(a0a, xp[0][2 * q + 1], kq.y);
                ffma2(a1a, xp[1][2 * q],     kq.x);
                ffma2(a1a, xp[1][2 * q + 1], kq.y);
            }
#pragma unroll
            for (int q = 2; q < 4; q++) {
                ulonglong2 kq = sk2[jj * 4 + q];
                ffma2(a0b, xp[0][2 * q],     kq.x);
                ffma2(a0b, xp[0][2 * q + 1], kq.y);
                ffma2(a1b, xp[1][2 * q],     kq.x);
                ffma2(a1b, xp[1][2 * q + 1], kq.y);
            }
            const float hkk = shkk[jj];
            float u, v;
            unpack2(add2(a0a, a0b), u, v);
            float s0 = (u + v) + hkk;
            unpack2(add2(a1a, a1b), u, v);
            float s1 = (u + v) + hkk;
            int j = j0 + jj;
            if (s0 > best0) { best0 = s0; bj0 = j; }  // strict > => first-index ties
            if (s1 > best1) { best1 = s1; bj1 = j; }
        }
    }

    // Epilogue: gather values -> qv, EMA atomic adds.
    int bj[2] = { bj0, bj1 };
#pragma unroll
    for (int p = 0; p < 2; p++) {
        int j = bj[p];
        const float4* vs = reinterpret_cast<const float4*>(values + ((size_t)c * J + j) * DK);
        float4* qd = reinterpret_cast<float4*>(out + OFF_QV + fi[p]);
#pragma unroll
        for (int q = 0; q < 4; q++) qd[q] = vs[q];

        atomicAdd(out + OFF_CS + c * J + j, OMD);
        float* ka = out + OFF_KA + ((size_t)(c * J + j)) * DK;
#pragma unroll
        for (int q = 0; q < 8; q++) {
            float a, b;
            unpack2(xp[p][q], a, b);
            atomicAdd(ka + 2 * q,     OMD * a);
            atomicAdd(ka + 2 * q + 1, OMD * b);
        }
    }
}

// ---------------- kernel 2: finalize new_keys --------------------------------
__global__ __launch_bounds__(256) void k_final(float* __restrict__ out) {
    __shared__ float sred[256];
    const int c = blockIdx.x, t = threadIdx.x;
    const float* ncs = out + OFF_CS + c * J;

    float part = 0.f;
    for (int j = t; j < J; j += 256) part += ncs[j];
    sred[t] = part;
    __syncthreads();
    for (int s = 128; s > 0; s >>= 1) {
        if (t < s) sred[t] += sred[t + s];
        __syncthreads();
    }
    const float tot = sred[0];
    const float scale = tot / (tot + (float)J * EPSV);

    for (int j = t; j < J; j += 256) {
        float cssm = (ncs[j] + EPSV) * scale;
        float inv = 1.0f / cssm;
        const float4* ka = reinterpret_cast<const float4*>(out + OFF_KA + (size_t)(c * J + j) * DK);
        float4* nk = reinterpret_cast<float4*>(out + OFF_KEYS + (size_t)(c * J + j) * DK);
#pragma unroll
        for (int q = 0; q < 4; q++) {
            float4 v = ka[q];
            v.x *= inv; v.y *= inv; v.z *= inv; v.w *= inv;
            nk[q] = v;
        }
    }
}

extern "C" void kernel_launch(void* const* d_in, const int* in_sizes, int n_in,
                              void* d_out, int out_size) {
    const float* x        = (const float*)d_in[0];
    const float* keys     = (const float*)d_in[1];
    const float* values   = (const float*)d_in[2];
    const float* keys_avg = (const float*)d_in[3];
    const float* cs       = (const float*)d_in[4];
    float* out = (float*)d_out;

    k_init<<<1024, 256>>>((const float4*)keys_avg, (const float4*)cs, (float4*)out);
    k_assign<<<512, 128>>>(x, keys, values, out);
    k_final<<<64, 256>>>(out);
}